// round 14
// baseline (speedup 1.0000x reference)
#include <cuda_runtime.h>
#include <cuda_fp16.h>
#include <math.h>
#include <stdint.h>

// Problem dims
#define BB 2
#define SS 2048
#define EE 2048
#define HH 16
#define KVH 4
#define HD 128
#define ROWS (BB * SS)    // 4096
#define NKV (KVH * HD)    // 512
#define NC (EE + 2 * NKV) // 3072

// ---------------------------------------------------------------------------
// Scratch (__device__ globals; no cudaMalloc allowed)
// ---------------------------------------------------------------------------
__device__ __half g_X[(size_t)ROWS * EE];        // x, fp16
__device__ __half g_Qb[(size_t)ROWS * EE];       // Q (rope+scale), fp16
__device__ __half g_Kb[(size_t)ROWS * NKV];      // K (rope), fp16
__device__ __half g_Vb[(size_t)ROWS * NKV];      // V, fp16
__device__ __half g_CX[(size_t)ROWS * EE];       // context, fp16
__device__ __half g_Wc[(size_t)NC * EE];         // QKV weights concat [N,K]
__device__ __half g_Wo[(size_t)EE * EE];         // Wo [N,K]

// ---------------------------------------------------------------------------
// MMA / cp.async helpers
// ---------------------------------------------------------------------------
__device__ __forceinline__ uint32_t smem_u32(const void* p) {
    uint32_t a;
    asm("{ .reg .u64 t; cvta.to.shared.u64 t, %1; cvt.u32.u64 %0, t; }"
        : "=r"(a) : "l"(p));
    return a;
}
__device__ __forceinline__ void ldsm_x4(uint32_t* r, uint32_t addr) {
    asm volatile("ldmatrix.sync.aligned.m8n8.x4.shared.b16 {%0,%1,%2,%3}, [%4];"
                 : "=r"(r[0]), "=r"(r[1]), "=r"(r[2]), "=r"(r[3]) : "r"(addr));
}
__device__ __forceinline__ void ldsm_x4_t(uint32_t* r, uint32_t addr) {
    asm volatile("ldmatrix.sync.aligned.m8n8.x4.trans.shared.b16 {%0,%1,%2,%3}, [%4];"
                 : "=r"(r[0]), "=r"(r[1]), "=r"(r[2]), "=r"(r[3]) : "r"(addr));
}
// fp16 HMMA m16n8k16, fp32 accumulate
__device__ __forceinline__ void mma16816h(float* c, const uint32_t* a,
                                          uint32_t b0, uint32_t b1) {
    asm volatile(
        "mma.sync.aligned.m16n8k16.row.col.f32.f16.f16.f32 "
        "{%0,%1,%2,%3}, {%4,%5,%6,%7}, {%8,%9}, {%0,%1,%2,%3};"
        : "+f"(c[0]), "+f"(c[1]), "+f"(c[2]), "+f"(c[3])
        : "r"(a[0]), "r"(a[1]), "r"(a[2]), "r"(a[3]), "r"(b0), "r"(b1));
}
__device__ __forceinline__ void cp16(uint32_t dst, const void* src) {
    asm volatile("cp.async.cg.shared.global [%0], [%1], 16;" :: "r"(dst), "l"(src));
}
__device__ __forceinline__ void cp_commit() {
    asm volatile("cp.async.commit_group;" ::: "memory");
}
template <int N> __device__ __forceinline__ void cp_wait() {
    asm volatile("cp.async.wait_group %0;" :: "n"(N) : "memory");
}
__device__ __forceinline__ float fex2(float x) {
    float r;
    asm("ex2.approx.f32 %0, %1;" : "=f"(r) : "f"(x));
    return r;
}
__device__ __forceinline__ uint32_t pack_h(__half a, __half b) {
    __half2 t(a, b);
    return *(uint32_t*)&t;
}
// write fp32 pair as fp16
__device__ __forceinline__ void wcvt(__half* __restrict__ H, size_t o,
                                     float a, float b) {
    *(uint32_t*)(H + o) = pack_h(__float2half_rn(a), __float2half_rn(b));
}

// ---------------------------------------------------------------------------
// fp32 -> fp16 convert (vectorized x4)
// ---------------------------------------------------------------------------
__global__ __launch_bounds__(256) void cvt_kernel(const float* __restrict__ in,
                                                  __half* __restrict__ out,
                                                  int n4) {
    int i = blockIdx.x * blockDim.x + threadIdx.x;
    if (i >= n4) return;
    float4 v = ((const float4*)in)[i];
    ((__half2*)out)[i * 2 + 0] = __half2(__float2half_rn(v.x), __float2half_rn(v.y));
    ((__half2*)out)[i * 2 + 1] = __half2(__float2half_rn(v.z), __float2half_rn(v.w));
}

// ---------------------------------------------------------------------------
// Fused weight transpose+convert: all 4 weights in ONE launch.
// Job table by flat block index:
//   [0,4096)      Wq  [2048,2048] -> Wc[0]
//   [4096,5120)   Wk  [2048,512]  -> Wc + EE*EE
//   [5120,6144)   Wv  [2048,512]  -> Wc + (EE+NKV)*EE
//   [6144,10240)  Wo  [2048,2048] -> Wob
// ---------------------------------------------------------------------------
__global__ __launch_bounds__(256) void wprep_kernel(
    const float* __restrict__ Wq, const float* __restrict__ Wk,
    const float* __restrict__ Wv, const float* __restrict__ Wo,
    __half* __restrict__ Wc, __half* __restrict__ Wob) {
    __shared__ float t[32][33];
    int bid = blockIdx.x;
    const float* in;
    __half* out;
    int Nd, bx;  // Nd = input row width; bx = block col index within job
    if (bid < 4096) {
        in = Wq; out = Wc; Nd = EE; bx = bid;
    } else if (bid < 5120) {
        in = Wk; out = Wc + (size_t)EE * EE; Nd = NKV; bx = bid - 4096;
    } else if (bid < 6144) {
        in = Wv; out = Wc + (size_t)(EE + NKV) * EE; Nd = NKV; bx = bid - 5120;
    } else {
        in = Wo; out = Wob; Nd = EE; bx = bid - 6144;
    }
    int nbx = Nd / 32;
    int n0 = (bx % nbx) * 32, k0 = (bx / nbx) * 32;
    int tx = threadIdx.x & 31, ty = threadIdx.x >> 5;
#pragma unroll
    for (int j = 0; j < 4; j++)
        t[ty + j * 8][tx] = in[(size_t)(k0 + ty + j * 8) * Nd + n0 + tx];
    __syncthreads();
#pragma unroll
    for (int j = 0; j < 4; j++)
        out[(size_t)(n0 + ty + j * 8) * EE + k0 + tx] =
            __float2half_rn(t[tx][ty + j * 8]);
}

// ---------------------------------------------------------------------------
// fp16 single-pass GEMM, persistent CTAs: C = A @ B^T, A [M,K], B [N,K].
// 128x128 tile, K-tile 64, 3-stage cp.async pipeline, occ 2.
// mode 0: fp32 C. mode 1: fused QKV epilogue (RoPE+scale, fp16 out).
// ---------------------------------------------------------------------------
#define GROW 72
#define GARR (128 * GROW * 2)        // 18432
#define GSTAGE_B (2 * GARR)          // 36864 (A, B)
#define GEMM_SMEM (3 * GSTAGE_B)     // 110592 -> occ 2
#define GEMM_GRID 296                // 148 SMs x occ 2

#define GLOAD(kc, st)                                                        \
    do {                                                                     \
        uint32_t uS = uBase + (st) * GSTAGE_B;                               \
        int koff = (kc) * 64;                                                \
        _Pragma("unroll") for (int t = 0; t < 4; t++) {                      \
            int idx = tid + t * 256;                                         \
            int r = idx >> 3, c8 = (idx & 7) * 8;                            \
            size_t go = (size_t)r * K + koff + c8;                           \
            uint32_t dso = (uint32_t)(r * (GROW * 2) + c8 * 2);              \
            cp16(uS + dso, gA + go);                                         \
            cp16(uS + GARR + dso, gB + go);                                  \
        }                                                                    \
    } while (0)

__global__ __launch_bounds__(256, 2) void gemm_mma(
    const __half* __restrict__ A, const __half* __restrict__ B,
    float* __restrict__ Cf,
    __half* __restrict__ Qo, __half* __restrict__ Ko, __half* __restrict__ Vo,
    int mode, int M, int N, int K) {
    extern __shared__ char gsm[];
    const uint32_t uBase = smem_u32(gsm);

    const int tid = threadIdx.x, wid = tid >> 5, lane = tid & 31;
    const int warp_m = (wid >> 2) * 64;
    const int warp_n = (wid & 3) * 32;

    const int a_roff = ((lane >> 3) & 1) * 8 + (lane & 7);
    const int a_coff = (lane >> 4) * 8;
    const int b_roff = (lane >> 4) * 8 + (lane & 7);
    const int b_coff = ((lane >> 3) & 1) * 8;
    const int cr = lane >> 2, cc = (lane & 3) * 2;

    const int nx = N >> 7;
    const int ntiles = (M >> 7) * nx;
    const int KC = K >> 6;

    for (int tix = blockIdx.x; tix < ntiles; tix += gridDim.x) {
        const int m0 = (tix / nx) * 128, n0 = (tix % nx) * 128;
        const __half* gA = A + (size_t)m0 * K;
        const __half* gB = B + (size_t)n0 * K;

        float acc[4][4][4];
#pragma unroll
        for (int i = 0; i < 4; i++)
#pragma unroll
            for (int j = 0; j < 4; j++)
#pragma unroll
                for (int c = 0; c < 4; c++) acc[i][j][c] = 0.f;

        __syncthreads();   // previous tile's smem reads done before refill
        GLOAD(0, 0);
        cp_commit();
        GLOAD(1, 1);
        cp_commit();

        int st = 0, stp = 2;
        for (int kc = 0; kc < KC; kc++) {
            if (kc + 1 < KC) cp_wait<1>(); else cp_wait<0>();
            __syncthreads();
            if (kc + 2 < KC) {
                GLOAD(kc + 2, stp);
                cp_commit();
            }

            const uint32_t uS = uBase + st * GSTAGE_B;
            const uint32_t uA = uS, uB = uS + GARR;

#pragma unroll
            for (int ks = 0; ks < 4; ks++) {
                uint32_t ah[4][4];
#pragma unroll
                for (int mt = 0; mt < 4; mt++) {
                    uint32_t off =
                        (uint32_t)((warp_m + mt * 16 + a_roff) * GROW +
                                   ks * 16 + a_coff) * 2;
                    ldsm_x4(ah[mt], uA + off);
                }
#pragma unroll
                for (int p = 0; p < 2; p++) {
                    uint32_t bf[4];
                    uint32_t off =
                        (uint32_t)((warp_n + p * 16 + b_roff) * GROW +
                                   ks * 16 + b_coff) * 2;
                    ldsm_x4(bf, uB + off);
#pragma unroll
                    for (int mt = 0; mt < 4; mt++) {
#pragma unroll
                        for (int hf = 0; hf < 2; hf++)
                            mma16816h(acc[mt][p * 2 + hf], ah[mt],
                                      bf[hf * 2], bf[hf * 2 + 1]);
                    }
                }
            }
            st = (st == 2) ? 0 : st + 1;
            stp = (stp == 2) ? 0 : stp + 1;
        }

        if (mode == 0) {
#pragma unroll
            for (int mt = 0; mt < 4; mt++) {
#pragma unroll
                for (int nt = 0; nt < 4; nt++) {
                    int row = m0 + warp_m + mt * 16 + cr;
                    int col = n0 + warp_n + nt * 8 + cc;
                    float* c = acc[mt][nt];
                    *(float2*)(Cf + (size_t)row * N + col) =
                        make_float2(c[0], c[1]);
                    *(float2*)(Cf + (size_t)(row + 8) * N + col) =
                        make_float2(c[2], c[3]);
                }
            }
        } else {
            // QKV fused epilogue: (col, col+1) is a RoPE rotation pair.
            // Q folds log2(e) so flash softmax uses raw ex2.
            const float qscale = 0.12751742f;  // log2(e)/sqrt(HD)
#pragma unroll
            for (int mt = 0; mt < 4; mt++) {
#pragma unroll
                for (int nt = 0; nt < 4; nt++) {
                    int row = m0 + warp_m + mt * 16 + cr;
                    int col = n0 + warp_n + nt * 8 + cc;
                    float* c = acc[mt][nt];
                    int s0 = row & (SS - 1);
                    if (col < EE) {
                        int i = (col & (HD - 1)) >> 1;
                        float f = exp2f(-(float)i * (13.287712379549449f / 64.0f));
                        float sn0, cs0, sn1, cs1;
                        sincosf((float)s0 * f, &sn0, &cs0);
                        sincosf((float)(s0 + 8) * f, &sn1, &cs1);
                        wcvt(Qo, (size_t)row * EE + col,
                             (c[0] * cs0 - c[1] * sn0) * qscale,
                             (c[0] * sn0 + c[1] * cs0) * qscale);
                        wcvt(Qo, (size_t)(row + 8) * EE + col,
                             (c[2] * cs1 - c[3] * sn1) * qscale,
                             (c[2] * sn1 + c[3] * cs1) * qscale);
                    } else if (col < EE + NKV) {
                        int colk = col - EE;
                        int i = (colk & (HD - 1)) >> 1;
                        float f = exp2f(-(float)i * (13.287712379549449f / 64.0f));
                        float sn0, cs0, sn1, cs1;
                        sincosf((float)s0 * f, &sn0, &cs0);
                        sincosf((float)(s0 + 8) * f, &sn1, &cs1);
                        wcvt(Ko, (size_t)row * NKV + colk,
                             c[0] * cs0 - c[1] * sn0, c[0] * sn0 + c[1] * cs0);
                        wcvt(Ko, (size_t)(row + 8) * NKV + colk,
                             c[2] * cs1 - c[3] * sn1, c[2] * sn1 + c[3] * cs1);
                    } else {
                        int colv = col - EE - NKV;
                        wcvt(Vo, (size_t)row * NKV + colv, c[0], c[1]);
                        wcvt(Vo, (size_t)(row + 8) * NKV + colv, c[2], c[3]);
                    }
                }
            }
        }
    }
}

// ---------------------------------------------------------------------------
// Flash attention, all-fp16 MMA (fp32 accum). BQ=128 (8 warps x 16 rows),
// BK=64, HD=128. Scores pre-scaled by log2(e). occ 2.
// Rescale of O accumulators skipped warp-uniformly when alpha==1 exactly.
// ---------------------------------------------------------------------------
#define FROW 136
#define FQ_B (128 * FROW * 2)        // 34816
#define FKV_B (64 * FROW * 2)        // 17408
#define FSTAGE_B (2 * FKV_B)         // 34816
#define FLA_SMEM (FQ_B + 2 * FSTAGE_B)   // 104448

#define KVLOAD(j, st)                                                         \
    do {                                                                      \
        uint32_t uS = uBase + FQ_B + (st) * FSTAGE_B;                         \
        _Pragma("unroll") for (int t = 0; t < 4; t++) {                       \
            int i = tid + t * 256;                                            \
            int r = i >> 4, c8 = (i & 15) << 3;                               \
            size_t g = (size_t)(b * SS + (j) * 64 + r) * NKV + kvh * HD + c8; \
            uint32_t dso = (uint32_t)(r * (FROW * 2) + c8 * 2);               \
            cp16(uS + dso, Kk + g);                                           \
            cp16(uS + FKV_B + dso, Vv + g);                                   \
        }                                                                     \
    } while (0)

__global__ __launch_bounds__(256, 2) void flash_mma(
    const __half* __restrict__ Q,
    const __half* __restrict__ Kk, const __half* __restrict__ Vv,
    __half* __restrict__ O) {
    extern __shared__ char fsm[];
    const uint32_t uBase = smem_u32(fsm);
    const uint32_t uQ = uBase;

    const int qt = gridDim.x - 1 - blockIdx.x;   // heavy tiles first
    const int h = blockIdx.y, b = blockIdx.z;
    const int kvh = h >> 2;
    const int tid = threadIdx.x, wid = tid >> 5, lane = tid & 31;
    const int cr = lane >> 2, tc = (lane & 3) << 1;

    const int a_roff = ((lane >> 3) & 1) * 8 + (lane & 7);
    const int a_coff = (lane >> 4) * 8;
    const int b_roff = (lane >> 4) * 8 + (lane & 7);
    const int b_coff = ((lane >> 3) & 1) * 8;
    const int v_roff = ((lane >> 3) & 1) * 8 + (lane & 7);
    const int v_coff = (lane >> 4) * 8;

    {
        const size_t qbase = (size_t)(b * SS + qt * 128) * EE + h * HD;
#pragma unroll
        for (int t = 0; t < 8; t++) {
            int i = tid + t * 256;
            int r = i >> 4, c8 = (i & 15) << 3;
            cp16(uQ + (uint32_t)(r * (FROW * 2) + c8 * 2),
                 Q + qbase + (size_t)r * EE + c8);
        }
        cp_commit();
    }
    KVLOAD(0, 0);
    cp_commit();

    float oacc[16][4];
#pragma unroll
    for (int i = 0; i < 16; i++)
#pragma unroll
        for (int c = 0; c < 4; c++) oacc[i][c] = 0.f;
    float m0 = -1e30f, m1 = -1e30f, l0 = 0.f, l1 = 0.f;

    const int border = qt * 128 + wid * 16;
    const int jmax = 2 * qt + 1;

    for (int j = 0; j <= jmax; j++) {
        if (j + 1 <= jmax) {
            KVLOAD(j + 1, (j + 1) & 1);
            cp_commit();
            cp_wait<1>();
        } else {
            cp_wait<0>();
        }
        __syncthreads();

        const uint32_t uS = uBase + FQ_B + (j & 1) * FSTAGE_B;
        const uint32_t uK = uS, uV = uS + FKV_B;

        if (j * 64 <= border + 15) {
            // ---- Scores S = Q @ K^T ----
            float sacc[8][4];
#pragma unroll
            for (int nt = 0; nt < 8; nt++)
#pragma unroll
                for (int c = 0; c < 4; c++) sacc[nt][c] = 0.f;

#pragma unroll
            for (int ks = 0; ks < 8; ks++) {
                uint32_t qf[4];
                ldsm_x4(qf, uQ + (uint32_t)((wid * 16 + a_roff) * FROW +
                                            ks * 16 + a_coff) * 2);
#pragma unroll
                for (int p = 0; p < 4; p++) {
                    uint32_t kf[4];
                    uint32_t off =
                        (uint32_t)((p * 16 + b_roff) * FROW +
                                   ks * 16 + b_coff) * 2;
                    ldsm_x4(kf, uK + off);
#pragma unroll
                    for (int hf = 0; hf < 2; hf++)
                        mma16816h(sacc[p * 2 + hf], qf, kf[hf * 2], kf[hf * 2 + 1]);
                }
            }

            if (j * 64 + 63 > border) {
                int qg0 = border + cr, qg1 = qg0 + 8;
#pragma unroll
                for (int nt = 0; nt < 8; nt++) {
                    int kg = j * 64 + nt * 8 + tc;
                    if (kg > qg0) sacc[nt][0] = -1e30f;
                    if (kg + 1 > qg0) sacc[nt][1] = -1e30f;
                    if (kg > qg1) sacc[nt][2] = -1e30f;
                    if (kg + 1 > qg1) sacc[nt][3] = -1e30f;
                }
            }

            float mx0 = -1e30f, mx1 = -1e30f;
#pragma unroll
            for (int nt = 0; nt < 8; nt++) {
                mx0 = fmaxf(mx0, fmaxf(sacc[nt][0], sacc[nt][1]));
                mx1 = fmaxf(mx1, fmaxf(sacc[nt][2], sacc[nt][3]));
            }
            mx0 = fmaxf(mx0, __shfl_xor_sync(0xffffffffu, mx0, 1, 4));
            mx0 = fmaxf(mx0, __shfl_xor_sync(0xffffffffu, mx0, 2, 4));
            mx1 = fmaxf(mx1, __shfl_xor_sync(0xffffffffu, mx1, 1, 4));
            mx1 = fmaxf(mx1, __shfl_xor_sync(0xffffffffu, mx1, 2, 4));
            float mn0 = fmaxf(m0, mx0), mn1 = fmaxf(m1, mx1);
            bool noresc = (mn0 == m0) && (mn1 == m1);
            float al0 = noresc ? 1.f : fex2(m0 - mn0);
            float al1 = noresc ? 1.f : fex2(m1 - mn1);

            float sum0 = 0.f, sum1 = 0.f;
            uint32_t ph[8][2];
#pragma unroll
            for (int nt = 0; nt < 8; nt++) {
                float p00 = fex2(sacc[nt][0] - mn0);
                float p01 = fex2(sacc[nt][1] - mn0);
                float p10 = fex2(sacc[nt][2] - mn1);
                float p11 = fex2(sacc[nt][3] - mn1);
                sum0 += p00 + p01;
                sum1 += p10 + p11;
                ph[nt][0] = pack_h(__float2half_rn(p00), __float2half_rn(p01));
                ph[nt][1] = pack_h(__float2half_rn(p10), __float2half_rn(p11));
            }
            sum0 += __shfl_xor_sync(0xffffffffu, sum0, 1, 4);
            sum0 += __shfl_xor_sync(0xffffffffu, sum0, 2, 4);
            sum1 += __shfl_xor_sync(0xffffffffu, sum1, 1, 4);
            sum1 += __shfl_xor_sync(0xffffffffu, sum1, 2, 4);
            l0 = l0 * al0 + sum0;
            l1 = l1 * al1 + sum1;
            m0 = mn0;
            m1 = mn1;
            if (!__all_sync(0xffffffffu, noresc)) {
#pragma unroll
                for (int nt = 0; nt < 16; nt++) {
                    oacc[nt][0] *= al0;
                    oacc[nt][1] *= al0;
                    oacc[nt][2] *= al1;
                    oacc[nt][3] *= al1;
                }
            }

            // ---- O += P @ V ----
#pragma unroll
            for (int ks = 0; ks < 4; ks++) {
                uint32_t ah4[4] = {ph[2 * ks][0], ph[2 * ks][1],
                                   ph[2 * ks + 1][0], ph[2 * ks + 1][1]};
#pragma unroll
                for (int p = 0; p < 8; p++) {
                    uint32_t vf[4];
                    uint32_t off =
                        (uint32_t)((ks * 16 + v_roff) * FROW +
                                   p * 16 + v_coff) * 2;
                    ldsm_x4_t(vf, uV + off);
#pragma unroll
                    for (int hf = 0; hf < 2; hf++)
                        mma16816h(oacc[p * 2 + hf], ah4, vf[hf * 2], vf[hf * 2 + 1]);
                }
            }
        }
        __syncthreads();
    }

    // ---- Epilogue: normalize + fp16 context ----
    float inv0 = 1.0f / l0, inv1 = 1.0f / l1;
    int row0 = qt * 128 + wid * 16 + cr;
    size_t obase = (size_t)(b * SS + row0) * EE + h * HD;
#pragma unroll
    for (int nt = 0; nt < 16; nt++) {
        int col = nt * 8 + tc;
        wcvt(O, obase + col, oacc[nt][0] * inv0, oacc[nt][1] * inv0);
        wcvt(O, obase + (size_t)8 * EE + col,
             oacc[nt][2] * inv1, oacc[nt][3] * inv1);
    }
}

// ---------------------------------------------------------------------------
// Launch
// ---------------------------------------------------------------------------
extern "C" void kernel_launch(void* const* d_in, const int* in_sizes, int n_in,
                              void* d_out, int out_size) {
    const float* x  = (const float*)d_in[0];
    const float* Wq = (const float*)d_in[1];
    const float* Wk = (const float*)d_in[2];
    const float* Wv = (const float*)d_in[3];
    const float* Wo = (const float*)d_in[4];

    __half *X, *Qb, *Kb, *Vb, *CX, *Wc, *Wob;
    cudaGetSymbolAddress((void**)&X, g_X);
    cudaGetSymbolAddress((void**)&Qb, g_Qb);
    cudaGetSymbolAddress((void**)&Kb, g_Kb);
    cudaGetSymbolAddress((void**)&Vb, g_Vb);
    cudaGetSymbolAddress((void**)&CX, g_CX);
    cudaGetSymbolAddress((void**)&Wc, g_Wc);
    cudaGetSymbolAddress((void**)&Wob, g_Wo);

    cudaFuncSetAttribute(gemm_mma, cudaFuncAttributeMaxDynamicSharedMemorySize,
                         GEMM_SMEM);
    cudaFuncSetAttribute(flash_mma, cudaFuncAttributeMaxDynamicSharedMemorySize,
                         FLA_SMEM);

    // Convert x; fused weight transpose+convert (one launch for all 4)
    cvt_kernel<<<(ROWS * EE / 4 + 255) / 256, 256>>>(x, X, ROWS * EE / 4);
    wprep_kernel<<<10240, 256>>>(Wq, Wk, Wv, Wo, Wc, Wob);

    // Fused QKV projection, persistent CTAs
    gemm_mma<<<GEMM_GRID, 256, GEMM_SMEM>>>(
        X, Wc, nullptr, Qb, Kb, Vb, 1, ROWS, NC, EE);

    // Flash attention (fp16 MMA, fp32 accum), occ 2
    flash_mma<<<dim3(SS / 128, HH, BB), 256, FLA_SMEM>>>(Qb, Kb, Vb, CX);

    // Output projection -> d_out (fp32), persistent CTAs
    gemm_mma<<<GEMM_GRID, 256, GEMM_SMEM>>>(
        CX, Wob, (float*)d_out, nullptr, nullptr, nullptr,
        0, ROWS, EE, EE);
}

// round 17
// speedup vs baseline: 1.1111x; 1.1111x over previous
#include <cuda_runtime.h>
#include <cuda_fp16.h>
#include <math.h>
#include <stdint.h>

// Problem dims
#define BB 2
#define SS 2048
#define EE 2048
#define HH 16
#define KVH 4
#define HD 128
#define ROWS (BB * SS)    // 4096
#define NKV (KVH * HD)    // 512
#define NC (EE + 2 * NKV) // 3072
#define NQT (SS / 128)    // 16 q-tiles

// ---------------------------------------------------------------------------
// Scratch (__device__ globals; no cudaMalloc allowed)
// ---------------------------------------------------------------------------
__device__ __half g_X[(size_t)ROWS * EE];
__device__ __half g_Qb[(size_t)ROWS * EE];
__device__ __half g_Kb[(size_t)ROWS * NKV];
__device__ __half g_Vb[(size_t)ROWS * NKV];
__device__ __half g_CX[(size_t)ROWS * EE];
__device__ __half g_Wc[(size_t)NC * EE];
__device__ __half g_Wo[(size_t)EE * EE];

// ---------------------------------------------------------------------------
// MMA / cp.async helpers
// ---------------------------------------------------------------------------
__device__ __forceinline__ uint32_t smem_u32(const void* p) {
    uint32_t a;
    asm("{ .reg .u64 t; cvta.to.shared.u64 t, %1; cvt.u32.u64 %0, t; }"
        : "=r"(a) : "l"(p));
    return a;
}
__device__ __forceinline__ void ldsm_x4(uint32_t* r, uint32_t addr) {
    asm volatile("ldmatrix.sync.aligned.m8n8.x4.shared.b16 {%0,%1,%2,%3}, [%4];"
                 : "=r"(r[0]), "=r"(r[1]), "=r"(r[2]), "=r"(r[3]) : "r"(addr));
}
__device__ __forceinline__ void ldsm_x4_t(uint32_t* r, uint32_t addr) {
    asm volatile("ldmatrix.sync.aligned.m8n8.x4.trans.shared.b16 {%0,%1,%2,%3}, [%4];"
                 : "=r"(r[0]), "=r"(r[1]), "=r"(r[2]), "=r"(r[3]) : "r"(addr));
}
__device__ __forceinline__ void mma16816h(float* c, const uint32_t* a,
                                          uint32_t b0, uint32_t b1) {
    asm volatile(
        "mma.sync.aligned.m16n8k16.row.col.f32.f16.f16.f32 "
        "{%0,%1,%2,%3}, {%4,%5,%6,%7}, {%8,%9}, {%0,%1,%2,%3};"
        : "+f"(c[0]), "+f"(c[1]), "+f"(c[2]), "+f"(c[3])
        : "r"(a[0]), "r"(a[1]), "r"(a[2]), "r"(a[3]), "r"(b0), "r"(b1));
}
__device__ __forceinline__ void cp16(uint32_t dst, const void* src) {
    asm volatile("cp.async.cg.shared.global [%0], [%1], 16;" :: "r"(dst), "l"(src));
}
__device__ __forceinline__ void cp_commit() {
    asm volatile("cp.async.commit_group;" ::: "memory");
}
template <int N> __device__ __forceinline__ void cp_wait() {
    asm volatile("cp.async.wait_group %0;" :: "n"(N) : "memory");
}
__device__ __forceinline__ float fex2(float x) {
    float r;
    asm("ex2.approx.f32 %0, %1;" : "=f"(r) : "f"(x));
    return r;
}
__device__ __forceinline__ uint32_t pack_h(__half a, __half b) {
    __half2 t(a, b);
    return *(uint32_t*)&t;
}
__device__ __forceinline__ void wcvt(__half* __restrict__ H, size_t o,
                                     float a, float b) {
    *(uint32_t*)(H + o) = pack_h(__float2half_rn(a), __float2half_rn(b));
}

// ---------------------------------------------------------------------------
// fp32 -> fp16 convert (vectorized x4)
// ---------------------------------------------------------------------------
__global__ __launch_bounds__(256) void cvt_kernel(const float* __restrict__ in,
                                                  __half* __restrict__ out,
                                                  int n4) {
    int i = blockIdx.x * blockDim.x + threadIdx.x;
    if (i >= n4) return;
    float4 v = ((const float4*)in)[i];
    ((__half2*)out)[i * 2 + 0] = __half2(__float2half_rn(v.x), __float2half_rn(v.y));
    ((__half2*)out)[i * 2 + 1] = __half2(__float2half_rn(v.z), __float2half_rn(v.w));
}

// ---------------------------------------------------------------------------
// Fused weight transpose+convert: all 4 weights in ONE launch.
// ---------------------------------------------------------------------------
__global__ __launch_bounds__(256) void wprep_kernel(
    const float* __restrict__ Wq, const float* __restrict__ Wk,
    const float* __restrict__ Wv, const float* __restrict__ Wo,
    __half* __restrict__ Wc, __half* __restrict__ Wob) {
    __shared__ float t[32][33];
    int bid = blockIdx.x;
    const float* in;
    __half* out;
    int Nd, bx;
    if (bid < 4096) {
        in = Wq; out = Wc; Nd = EE; bx = bid;
    } else if (bid < 5120) {
        in = Wk; out = Wc + (size_t)EE * EE; Nd = NKV; bx = bid - 4096;
    } else if (bid < 6144) {
        in = Wv; out = Wc + (size_t)(EE + NKV) * EE; Nd = NKV; bx = bid - 5120;
    } else {
        in = Wo; out = Wob; Nd = EE; bx = bid - 6144;
    }
    int nbx = Nd / 32;
    int n0 = (bx % nbx) * 32, k0 = (bx / nbx) * 32;
    int tx = threadIdx.x & 31, ty = threadIdx.x >> 5;
#pragma unroll
    for (int j = 0; j < 4; j++)
        t[ty + j * 8][tx] = in[(size_t)(k0 + ty + j * 8) * Nd + n0 + tx];
    __syncthreads();
#pragma unroll
    for (int j = 0; j < 4; j++)
        out[(size_t)(n0 + ty + j * 8) * EE + k0 + tx] =
            __float2half_rn(t[tx][ty + j * 8]);
}

// ---------------------------------------------------------------------------
// fp16 single-pass GEMM (R12 structure: one tile per CTA).
// 128x128 tile, K-tile 64, 3-stage cp.async pipeline, occ 2.
// mode 0: fp32 C. mode 1: fused QKV epilogue (RoPE+scale, fp16 out).
// ---------------------------------------------------------------------------
#define GROW 72
#define GARR (128 * GROW * 2)        // 18432
#define GSTAGE_B (2 * GARR)          // 36864
#define GEMM_SMEM (3 * GSTAGE_B)     // 110592 -> occ 2

#define GLOAD(kc, st)                                                        \
    do {                                                                     \
        uint32_t uS = uBase + (st) * GSTAGE_B;                               \
        int koff = (kc) * 64;                                                \
        _Pragma("unroll") for (int t = 0; t < 4; t++) {                      \
            int idx = tid + t * 256;                                         \
            int r = idx >> 3, c8 = (idx & 7) * 8;                            \
            size_t go = (size_t)r * K + koff + c8;                           \
            uint32_t dso = (uint32_t)(r * (GROW * 2) + c8 * 2);              \
            cp16(uS + dso, gA + go);                                         \
            cp16(uS + GARR + dso, gB + go);                                  \
        }                                                                    \
    } while (0)

__global__ __launch_bounds__(256, 2) void gemm_mma(
    const __half* __restrict__ A, const __half* __restrict__ B,
    float* __restrict__ Cf,
    __half* __restrict__ Qo, __half* __restrict__ Ko, __half* __restrict__ Vo,
    int mode, int M, int N, int K) {
    extern __shared__ char gsm[];
    const uint32_t uBase = smem_u32(gsm);

    const int tid = threadIdx.x, wid = tid >> 5, lane = tid & 31;
    const int m0 = blockIdx.y * 128, n0 = blockIdx.x * 128;
    const int warp_m = (wid >> 2) * 64;
    const int warp_n = (wid & 3) * 32;

    const int a_roff = ((lane >> 3) & 1) * 8 + (lane & 7);
    const int a_coff = (lane >> 4) * 8;
    const int b_roff = (lane >> 4) * 8 + (lane & 7);
    const int b_coff = ((lane >> 3) & 1) * 8;

    float acc[4][4][4];
#pragma unroll
    for (int i = 0; i < 4; i++)
#pragma unroll
        for (int j = 0; j < 4; j++)
#pragma unroll
            for (int c = 0; c < 4; c++) acc[i][j][c] = 0.f;

    const __half* gA = A + (size_t)m0 * K;
    const __half* gB = B + (size_t)n0 * K;

    const int KC = K >> 6;
    GLOAD(0, 0);
    cp_commit();
    GLOAD(1, 1);
    cp_commit();

    int st = 0, stp = 2;
    for (int kc = 0; kc < KC; kc++) {
        if (kc + 1 < KC) cp_wait<1>(); else cp_wait<0>();
        __syncthreads();
        if (kc + 2 < KC) {
            GLOAD(kc + 2, stp);
            cp_commit();
        }

        const uint32_t uS = uBase + st * GSTAGE_B;
        const uint32_t uA = uS, uB = uS + GARR;

#pragma unroll
        for (int ks = 0; ks < 4; ks++) {
            uint32_t ah[4][4];
#pragma unroll
            for (int mt = 0; mt < 4; mt++) {
                uint32_t off =
                    (uint32_t)((warp_m + mt * 16 + a_roff) * GROW +
                               ks * 16 + a_coff) * 2;
                ldsm_x4(ah[mt], uA + off);
            }
#pragma unroll
            for (int p = 0; p < 2; p++) {
                uint32_t bf[4];
                uint32_t off =
                    (uint32_t)((warp_n + p * 16 + b_roff) * GROW +
                               ks * 16 + b_coff) * 2;
                ldsm_x4(bf, uB + off);
#pragma unroll
                for (int mt = 0; mt < 4; mt++) {
#pragma unroll
                    for (int hf = 0; hf < 2; hf++)
                        mma16816h(acc[mt][p * 2 + hf], ah[mt],
                                  bf[hf * 2], bf[hf * 2 + 1]);
                }
            }
        }
        st = (st == 2) ? 0 : st + 1;
        stp = (stp == 2) ? 0 : stp + 1;
    }

    const int cr = lane >> 2, cc = (lane & 3) * 2;
    if (mode == 0) {
#pragma unroll
        for (int mt = 0; mt < 4; mt++) {
#pragma unroll
            for (int nt = 0; nt < 4; nt++) {
                int row = m0 + warp_m + mt * 16 + cr;
                int col = n0 + warp_n + nt * 8 + cc;
                float* c = acc[mt][nt];
                *(float2*)(Cf + (size_t)row * N + col) = make_float2(c[0], c[1]);
                *(float2*)(Cf + (size_t)(row + 8) * N + col) =
                    make_float2(c[2], c[3]);
            }
        }
    } else {
        const float qscale = 0.12751742f;  // log2(e)/sqrt(HD)
#pragma unroll
        for (int mt = 0; mt < 4; mt++) {
#pragma unroll
            for (int nt = 0; nt < 4; nt++) {
                int row = m0 + warp_m + mt * 16 + cr;
                int col = n0 + warp_n + nt * 8 + cc;
                float* c = acc[mt][nt];
                int s0 = row & (SS - 1);
                if (col < EE) {
                    int i = (col & (HD - 1)) >> 1;
                    float f = exp2f(-(float)i * (13.287712379549449f / 64.0f));
                    float sn0, cs0, sn1, cs1;
                    sincosf((float)s0 * f, &sn0, &cs0);
                    sincosf((float)(s0 + 8) * f, &sn1, &cs1);
                    wcvt(Qo, (size_t)row * EE + col,
                         (c[0] * cs0 - c[1] * sn0) * qscale,
                         (c[0] * sn0 + c[1] * cs0) * qscale);
                    wcvt(Qo, (size_t)(row + 8) * EE + col,
                         (c[2] * cs1 - c[3] * sn1) * qscale,
                         (c[2] * sn1 + c[3] * cs1) * qscale);
                } else if (col < EE + NKV) {
                    int colk = col - EE;
                    int i = (colk & (HD - 1)) >> 1;
                    float f = exp2f(-(float)i * (13.287712379549449f / 64.0f));
                    float sn0, cs0, sn1, cs1;
                    sincosf((float)s0 * f, &sn0, &cs0);
                    sincosf((float)(s0 + 8) * f, &sn1, &cs1);
                    wcvt(Ko, (size_t)row * NKV + colk,
                         c[0] * cs0 - c[1] * sn0, c[0] * sn0 + c[1] * cs0);
                    wcvt(Ko, (size_t)(row + 8) * NKV + colk,
                         c[2] * cs1 - c[3] * sn1, c[2] * sn1 + c[3] * cs1);
                } else {
                    int colv = col - EE - NKV;
                    wcvt(Vo, (size_t)row * NKV + colv, c[0], c[1]);
                    wcvt(Vo, (size_t)(row + 8) * NKV + colv, c[2], c[3]);
                }
            }
        }
    }
}

// ---------------------------------------------------------------------------
// Flash attention, all-fp16 MMA (fp32 accum). BQ=128 (8 warps x 16 rows),
// BK=64, HD=128. Scores pre-scaled by log2(e). occ 2.
// Work-balanced: each CTA processes the complementary q-tile pair
// (x, NQT-1-x) sequentially -> every CTA does exactly 2*NQT+2 KV-tiles,
// grid = NQT/2 x HH x BB = one balanced wave.
// ---------------------------------------------------------------------------
#define FROW 136
#define FQ_B (128 * FROW * 2)        // 34816
#define FKV_B (64 * FROW * 2)        // 17408
#define FSTAGE_B (2 * FKV_B)         // 34816
#define FLA_SMEM (FQ_B + 2 * FSTAGE_B)   // 104448

#define KVLOAD(j, st)                                                         \
    do {                                                                      \
        uint32_t uS = uBase + FQ_B + (st) * FSTAGE_B;                         \
        _Pragma("unroll") for (int t = 0; t < 4; t++) {                       \
            int i = tid + t * 256;                                            \
            int r = i >> 4, c8 = (i & 15) << 3;                               \
            size_t g = (size_t)(b * SS + (j) * 64 + r) * NKV + kvh * HD + c8; \
            uint32_t dso = (uint32_t)(r * (FROW * 2) + c8 * 2);               \
            cp16(uS + dso, Kk + g);                                           \
            cp16(uS + FKV_B + dso, Vv + g);                                   \
        }                                                                     \
    } while (0)

__global__ __launch_bounds__(256, 2) void flash_mma(
    const __half* __restrict__ Q,
    const __half* __restrict__ Kk, const __half* __restrict__ Vv,
    __half* __restrict__ O) {
    extern __shared__ char fsm[];
    const uint32_t uBase = smem_u32(fsm);
    const uint32_t uQ = uBase;

    const int h = blockIdx.y, b = blockIdx.z;
    const int kvh = h >> 2;
    const int tid = threadIdx.x, wid = tid >> 5, lane = tid & 31;
    const int cr = lane >> 2, tc = (lane & 3) << 1;

    const int a_roff = ((lane >> 3) & 1) * 8 + (lane & 7);
    const int a_coff = (lane >> 4) * 8;
    const int b_roff = (lane >> 4) * 8 + (lane & 7);
    const int b_coff = ((lane >> 3) & 1) * 8;
    const int v_roff = ((lane >> 3) & 1) * 8 + (lane & 7);
    const int v_coff = (lane >> 4) * 8;

#pragma unroll 1
    for (int pass = 0; pass < 2; pass++) {
        // Complementary pair: heavy tile first, then light
        const int qt = pass == 0 ? (NQT - 1 - blockIdx.x) : blockIdx.x;

        if (pass) __syncthreads();   // drain smem reads of previous pass

        {
            const size_t qbase = (size_t)(b * SS + qt * 128) * EE + h * HD;
#pragma unroll
            for (int t = 0; t < 8; t++) {
                int i = tid + t * 256;
                int r = i >> 4, c8 = (i & 15) << 3;
                cp16(uQ + (uint32_t)(r * (FROW * 2) + c8 * 2),
                     Q + qbase + (size_t)r * EE + c8);
            }
            cp_commit();
        }
        KVLOAD(0, 0);
        cp_commit();

        float oacc[16][4];
#pragma unroll
        for (int i = 0; i < 16; i++)
#pragma unroll
            for (int c = 0; c < 4; c++) oacc[i][c] = 0.f;
        float m0 = -1e30f, m1 = -1e30f, l0 = 0.f, l1 = 0.f;

        const int border = qt * 128 + wid * 16;
        const int jmax = 2 * qt + 1;

        for (int j = 0; j <= jmax; j++) {
            if (j + 1 <= jmax) {
                KVLOAD(j + 1, (j + 1) & 1);
                cp_commit();
                cp_wait<1>();
            } else {
                cp_wait<0>();
            }
            __syncthreads();

            const uint32_t uS = uBase + FQ_B + (j & 1) * FSTAGE_B;
            const uint32_t uK = uS, uV = uS + FKV_B;

            if (j * 64 <= border + 15) {
                // ---- Scores S = Q @ K^T ----
                float sacc[8][4];
#pragma unroll
                for (int nt = 0; nt < 8; nt++)
#pragma unroll
                    for (int c = 0; c < 4; c++) sacc[nt][c] = 0.f;

#pragma unroll
                for (int ks = 0; ks < 8; ks++) {
                    uint32_t qf[4];
                    ldsm_x4(qf, uQ + (uint32_t)((wid * 16 + a_roff) * FROW +
                                                ks * 16 + a_coff) * 2);
#pragma unroll
                    for (int p = 0; p < 4; p++) {
                        uint32_t kf[4];
                        uint32_t off =
                            (uint32_t)((p * 16 + b_roff) * FROW +
                                       ks * 16 + b_coff) * 2;
                        ldsm_x4(kf, uK + off);
#pragma unroll
                        for (int hf = 0; hf < 2; hf++)
                            mma16816h(sacc[p * 2 + hf], qf,
                                      kf[hf * 2], kf[hf * 2 + 1]);
                    }
                }

                if (j * 64 + 63 > border) {
                    int qg0 = border + cr, qg1 = qg0 + 8;
#pragma unroll
                    for (int nt = 0; nt < 8; nt++) {
                        int kg = j * 64 + nt * 8 + tc;
                        if (kg > qg0) sacc[nt][0] = -1e30f;
                        if (kg + 1 > qg0) sacc[nt][1] = -1e30f;
                        if (kg > qg1) sacc[nt][2] = -1e30f;
                        if (kg + 1 > qg1) sacc[nt][3] = -1e30f;
                    }
                }

                float mx0 = -1e30f, mx1 = -1e30f;
#pragma unroll
                for (int nt = 0; nt < 8; nt++) {
                    mx0 = fmaxf(mx0, fmaxf(sacc[nt][0], sacc[nt][1]));
                    mx1 = fmaxf(mx1, fmaxf(sacc[nt][2], sacc[nt][3]));
                }
                mx0 = fmaxf(mx0, __shfl_xor_sync(0xffffffffu, mx0, 1, 4));
                mx0 = fmaxf(mx0, __shfl_xor_sync(0xffffffffu, mx0, 2, 4));
                mx1 = fmaxf(mx1, __shfl_xor_sync(0xffffffffu, mx1, 1, 4));
                mx1 = fmaxf(mx1, __shfl_xor_sync(0xffffffffu, mx1, 2, 4));
                float mn0 = fmaxf(m0, mx0), mn1 = fmaxf(m1, mx1);
                bool noresc = (mn0 == m0) && (mn1 == m1);
                float al0 = noresc ? 1.f : fex2(m0 - mn0);
                float al1 = noresc ? 1.f : fex2(m1 - mn1);

                float sum0 = 0.f, sum1 = 0.f;
                uint32_t ph[8][2];
#pragma unroll
                for (int nt = 0; nt < 8; nt++) {
                    float p00 = fex2(sacc[nt][0] - mn0);
                    float p01 = fex2(sacc[nt][1] - mn0);
                    float p10 = fex2(sacc[nt][2] - mn1);
                    float p11 = fex2(sacc[nt][3] - mn1);
                    sum0 += p00 + p01;
                    sum1 += p10 + p11;
                    ph[nt][0] = pack_h(__float2half_rn(p00), __float2half_rn(p01));
                    ph[nt][1] = pack_h(__float2half_rn(p10), __float2half_rn(p11));
                }
                sum0 += __shfl_xor_sync(0xffffffffu, sum0, 1, 4);
                sum0 += __shfl_xor_sync(0xffffffffu, sum0, 2, 4);
                sum1 += __shfl_xor_sync(0xffffffffu, sum1, 1, 4);
                sum1 += __shfl_xor_sync(0xffffffffu, sum1, 2, 4);
                l0 = l0 * al0 + sum0;
                l1 = l1 * al1 + sum1;
                m0 = mn0;
                m1 = mn1;
                if (!__all_sync(0xffffffffu, noresc)) {
#pragma unroll
                    for (int nt = 0; nt < 16; nt++) {
                        oacc[nt][0] *= al0;
                        oacc[nt][1] *= al0;
                        oacc[nt][2] *= al1;
                        oacc[nt][3] *= al1;
                    }
                }

                // ---- O += P @ V ----
#pragma unroll
                for (int ks = 0; ks < 4; ks++) {
                    uint32_t ah4[4] = {ph[2 * ks][0], ph[2 * ks][1],
                                       ph[2 * ks + 1][0], ph[2 * ks + 1][1]};
#pragma unroll
                    for (int p = 0; p < 8; p++) {
                        uint32_t vf[4];
                        uint32_t off =
                            (uint32_t)((ks * 16 + v_roff) * FROW +
                                       p * 16 + v_coff) * 2;
                        ldsm_x4_t(vf, uV + off);
#pragma unroll
                        for (int hf = 0; hf < 2; hf++)
                            mma16816h(oacc[p * 2 + hf], ah4,
                                      vf[hf * 2], vf[hf * 2 + 1]);
                    }
                }
            }
            __syncthreads();
        }

        // ---- Epilogue: normalize + fp16 context ----
        float inv0 = 1.0f / l0, inv1 = 1.0f / l1;
        int row0 = qt * 128 + wid * 16 + cr;
        size_t obase = (size_t)(b * SS + row0) * EE + h * HD;
#pragma unroll
        for (int nt = 0; nt < 16; nt++) {
            int col = nt * 8 + tc;
            wcvt(O, obase + col, oacc[nt][0] * inv0, oacc[nt][1] * inv0);
            wcvt(O, obase + (size_t)8 * EE + col,
                 oacc[nt][2] * inv1, oacc[nt][3] * inv1);
        }
    }
}

// ---------------------------------------------------------------------------
// Launch
// ---------------------------------------------------------------------------
extern "C" void kernel_launch(void* const* d_in, const int* in_sizes, int n_in,
                              void* d_out, int out_size) {
    const float* x  = (const float*)d_in[0];
    const float* Wq = (const float*)d_in[1];
    const float* Wk = (const float*)d_in[2];
    const float* Wv = (const float*)d_in[3];
    const float* Wo = (const float*)d_in[4];

    __half *X, *Qb, *Kb, *Vb, *CX, *Wc, *Wob;
    cudaGetSymbolAddress((void**)&X, g_X);
    cudaGetSymbolAddress((void**)&Qb, g_Qb);
    cudaGetSymbolAddress((void**)&Kb, g_Kb);
    cudaGetSymbolAddress((void**)&Vb, g_Vb);
    cudaGetSymbolAddress((void**)&CX, g_CX);
    cudaGetSymbolAddress((void**)&Wc, g_Wc);
    cudaGetSymbolAddress((void**)&Wob, g_Wo);

    cudaFuncSetAttribute(gemm_mma, cudaFuncAttributeMaxDynamicSharedMemorySize,
                         GEMM_SMEM);
    cudaFuncSetAttribute(flash_mma, cudaFuncAttributeMaxDynamicSharedMemorySize,
                         FLA_SMEM);

    // Convert x; fused weight transpose+convert
    cvt_kernel<<<(ROWS * EE / 4 + 255) / 256, 256>>>(x, X, ROWS * EE / 4);
    wprep_kernel<<<10240, 256>>>(Wq, Wk, Wv, Wo, Wc, Wob);

    // Fused QKV projection (plain grid)
    gemm_mma<<<dim3(NC / 128, ROWS / 128), 256, GEMM_SMEM>>>(
        X, Wc, nullptr, Qb, Kb, Vb, 1, ROWS, NC, EE);

    // Flash attention, balanced complementary-pair scheduling (1 wave)
    flash_mma<<<dim3(NQT / 2, HH, BB), 256, FLA_SMEM>>>(Qb, Kb, Vb, CX);

    // Output projection -> d_out (fp32)
    gemm_mma<<<dim3(EE / 128, ROWS / 128), 256, GEMM_SMEM>>>(
        CX, Wob, (float*)d_out, nullptr, nullptr, nullptr,
        0, ROWS, EE, EE);
}